// round 15
// baseline (speedup 1.0000x reference)
#include <cuda_runtime.h>
#include <cuda_bf16.h>
#include <math.h>

// ---------------------------------------------------------------------------
// GPT-2 small forward. fp32 activations; GEMMs use split-bf16 (3xBF16)
// mma.sync.m16n8k16 on pre-split/pre-packed operands. Attention is a fused
// flash kernel (S=QK^T, online softmax in registers, P*V with P fragments
// taken directly from S accumulators). Linear GEMMs: KT=32 double-buffered.
// ---------------------------------------------------------------------------

namespace {
constexpr int B_  = 4;
constexpr int T_  = 1024;
constexpr int C_  = 768;
constexpr int H_  = 12;
constexpr int HS_ = 64;
constexpr int L_  = 12;
constexpr int V_  = 32000;
constexpr int BT_ = B_ * T_;
constexpr int C4_ = 4 * C_;
constexpr int C3_ = 3 * C_;

constexpr int P2  = 132;                // B smem row pitch in uint2

// linear GEMM 128x128 (KT=32)
constexpr int K2L   = 16;
constexpr int STGL  = 2 * K2L * P2;
constexpr size_t SMEM_LIN = 2 * STGL * sizeof(uint2);     // 67584 B

// linear GEMM 64x128 (KT=32), A-pitch 68
constexpr int PA64  = 68;
constexpr int STG64 = K2L * PA64 + K2L * P2;
constexpr size_t SMEM_L64 = 2 * STG64 * sizeof(uint2);    // 51200 B

// fused attention: Qs[32][132] + Ks[32][68] + Vs[32][68] (uint2)
constexpr int FA_QS = 32 * 132;
constexpr int FA_KS = 32 * 68;
constexpr size_t SMEM_FA = (FA_QS + 2 * FA_KS) * sizeof(uint2);  // 68608 B
}

// Scratch (no cudaMalloc -> device globals)
__device__ float    g_x   [BT_ * C_];
__device__ uint2    g_h2  [BT_ * C_ / 2];      // PP: [row][C/2]
__device__ unsigned g_qkv2[BT_ * C3_];         // EW u32 per element
__device__ uint2    g_o2  [BT_ * C_ / 2];      // PP
__device__ uint2    g_a12 [BT_ * C4_ / 2];     // PP
// all-layer pre-split packed weights: [k2][n] uint2
__device__ uint2 g_wcat2[(size_t)L_ * (C_ / 2) * C3_];
__device__ uint2 g_wp2  [(size_t)L_ * (C_ / 2) * C_];
__device__ uint2 g_w12  [(size_t)L_ * (C_ / 2) * C4_];
__device__ uint2 g_w22  [(size_t)L_ * (C4_ / 2) * C_];
__device__ uint2 g_wh2  [(size_t)(C_ / 2) * V_];

// ---------------------------------------------------------------------------
// bf16 split helpers
// ---------------------------------------------------------------------------
__device__ __forceinline__ unsigned splitbf(float x) {
    __nv_bfloat16 h = __float2bfloat16(x);
    float hf = __bfloat162float(h);
    __nv_bfloat16 l = __float2bfloat16(x - hf);
    return (unsigned)__bfloat16_as_ushort(h) |
           ((unsigned)__bfloat16_as_ushort(l) << 16);
}

#define HIPAIR(e0, e1) __byte_perm((e0), (e1), 0x5410)
#define LOPAIR(e0, e1) __byte_perm((e0), (e1), 0x7632)

__device__ __forceinline__ uint2 packpair(float a, float b) {
    unsigned u0 = splitbf(a), u1 = splitbf(b);
    return make_uint2(HIPAIR(u0, u1), LOPAIR(u0, u1));
}

__device__ __forceinline__ void mma_bf16(float* d, const unsigned* a,
                                         unsigned b0, unsigned b1) {
    asm volatile(
        "mma.sync.aligned.m16n8k16.row.col.f32.bf16.bf16.f32 "
        "{%0,%1,%2,%3}, {%4,%5,%6,%7}, {%8,%9}, {%0,%1,%2,%3};"
        : "+f"(d[0]), "+f"(d[1]), "+f"(d[2]), "+f"(d[3])
        : "r"(a[0]), "r"(a[1]), "r"(a[2]), "r"(a[3]),
          "r"(b0), "r"(b1));
}

// ---------------------------------------------------------------------------
// Linear GEMM 128x128, KT=32, 512 threads, 16 warps (4x4), warp tile 32x32.
// A: PP [M][K/2] uint2.  B: PP [K/2][N] uint2.
// outMode: 0 plain float, 1 EW u32, 2 PP uint2.
// ---------------------------------------------------------------------------
__global__ void __launch_bounds__(512)
gemm_lin(const uint2* __restrict__ A, const uint2* __restrict__ Bw,
         float* __restrict__ Cp, int M, int N, int K,
         const float* __restrict__ bias, const float* __restrict__ resid,
         int doGelu, int outMode)
{
    extern __shared__ uint2 smbuf[];
    const int ldaH = K >> 1;

    int m0   = blockIdx.y << 7;
    int n0   = blockIdx.x << 7;
    int tid  = threadIdx.x;
    int lane = tid & 31;
    int wid  = tid >> 5;
    int wm   = (wid & 3) << 5;
    int wn   = (wid >> 2) << 5;

    float acc[2][4][4];
    #pragma unroll
    for (int a = 0; a < 2; a++)
        #pragma unroll
        for (int b = 0; b < 4; b++)
            #pragma unroll
            for (int j = 0; j < 4; j++) acc[a][b][j] = 0.f;

    const int la_m  = tid >> 2;
    const int la_k2 = (tid & 3) << 2;
    const int lb_k2 = tid >> 5;
    const int lb_n  = (tid & 31) << 2;

    uint4 ra[2], rb[2];
    const int nk = K >> 5;

    auto LOAD = [&](int kh) {
        const uint4* pa = (const uint4*)(A + (size_t)(m0 + la_m) * ldaH + (kh + la_k2));
        ra[0] = pa[0]; ra[1] = pa[1];
        const uint4* pb = (const uint4*)(Bw + (size_t)(kh + lb_k2) * N + (n0 + lb_n));
        rb[0] = pb[0]; rb[1] = pb[1];
    };
    auto STORE = [&](int s) {
        uint2* As = smbuf + s * STGL;
        uint2* Bs = As + K2L * P2;
        As[(la_k2 + 0) * P2 + la_m] = make_uint2(ra[0].x, ra[0].y);
        As[(la_k2 + 1) * P2 + la_m] = make_uint2(ra[0].z, ra[0].w);
        As[(la_k2 + 2) * P2 + la_m] = make_uint2(ra[1].x, ra[1].y);
        As[(la_k2 + 3) * P2 + la_m] = make_uint2(ra[1].z, ra[1].w);
        *(uint4*)&Bs[lb_k2 * P2 + lb_n]     = rb[0];
        *(uint4*)&Bs[lb_k2 * P2 + lb_n + 2] = rb[1];
    };

    LOAD(0);
    STORE(0);
    __syncthreads();

    for (int t = 0; t < nk; t++) {
        if (t + 1 < nk) LOAD((t + 1) << 4);

        const uint2* As = smbuf + (t & 1) * STGL;
        const uint2* Bs = As + K2L * P2;

        #pragma unroll
        for (int kh = 0; kh < 2; kh++) {
            int k2q = (kh << 3) + (lane & 3);
            int qd  = lane >> 2;
            uint2 aA[2][4];
            #pragma unroll
            for (int mt = 0; mt < 2; mt++) {
                int r = wm + (mt << 4) + qd;
                aA[mt][0] = As[ k2q      * P2 + r];
                aA[mt][1] = As[ k2q      * P2 + r + 8];
                aA[mt][2] = As[(k2q + 4) * P2 + r];
                aA[mt][3] = As[(k2q + 4) * P2 + r + 8];
            }
            uint2 bB[4][2];
            #pragma unroll
            for (int nt = 0; nt < 4; nt++) {
                int cn = wn + (nt << 3) + qd;
                bB[nt][0] = Bs[ k2q      * P2 + cn];
                bB[nt][1] = Bs[(k2q + 4) * P2 + cn];
            }
            #pragma unroll
            for (int mt = 0; mt < 2; mt++) {
                unsigned ah[4] = {aA[mt][0].x, aA[mt][1].x, aA[mt][2].x, aA[mt][3].x};
                unsigned al[4] = {aA[mt][0].y, aA[mt][1].y, aA[mt][2].y, aA[mt][3].y};
                #pragma unroll
                for (int nt = 0; nt < 4; nt++) {
                    mma_bf16(acc[mt][nt], ah, bB[nt][0].x, bB[nt][1].x);
                    mma_bf16(acc[mt][nt], ah, bB[nt][0].y, bB[nt][1].y);
                    mma_bf16(acc[mt][nt], al, bB[nt][0].x, bB[nt][1].x);
                }
            }
        }

        if (t + 1 < nk) STORE((t + 1) & 1);
        __syncthreads();
    }

    unsigned* Cu = (unsigned*)Cp;
    uint2*    Cq = (uint2*)Cp;
    #pragma unroll
    for (int mt = 0; mt < 2; mt++) {
        #pragma unroll
        for (int nt = 0; nt < 4; nt++) {
            int row = m0 + wm + (mt << 4) + (lane >> 2);
            int col = n0 + wn + (nt << 3) + ((lane & 3) << 1);
            float v[4];
            #pragma unroll
            for (int j = 0; j < 4; j++) {
                int r = row + ((j & 2) ? 8 : 0);
                int c = col + (j & 1);
                float vv = acc[mt][nt][j];
                if (bias) vv += bias[c];
                if (doGelu) vv = 0.5f * vv * (1.f + erff(vv * 0.70710678118654752f));
                if (resid) vv += resid[(size_t)r * N + c];
                v[j] = vv;
            }
            if (outMode == 0) {
                *(float2*)&Cp[(size_t)row * N + col]       = make_float2(v[0], v[1]);
                *(float2*)&Cp[(size_t)(row + 8) * N + col] = make_float2(v[2], v[3]);
            } else if (outMode == 1) {
                Cu[(size_t)row * N + col]           = splitbf(v[0]);
                Cu[(size_t)row * N + col + 1]       = splitbf(v[1]);
                Cu[(size_t)(row + 8) * N + col]     = splitbf(v[2]);
                Cu[(size_t)(row + 8) * N + col + 1] = splitbf(v[3]);
            } else {
                Cq[(size_t)row * (N >> 1) + (col >> 1)]       = packpair(v[0], v[1]);
                Cq[(size_t)(row + 8) * (N >> 1) + (col >> 1)] = packpair(v[2], v[3]);
            }
        }
    }
}

// ---------------------------------------------------------------------------
// Linear GEMM 64x128, KT=32, 256 threads, 8 warps (2x4). 2 CTAs/SM.
// Plain-float output with bias+resid (proj and fc2).
// ---------------------------------------------------------------------------
__global__ void __launch_bounds__(256, 2)
gemm_lin64(const uint2* __restrict__ A, const uint2* __restrict__ Bw,
           float* __restrict__ Cp, int N, int K,
           const float* __restrict__ bias, const float* __restrict__ resid)
{
    extern __shared__ uint2 smbuf[];
    const int ldaH = K >> 1;

    int m0   = blockIdx.y << 6;
    int n0   = blockIdx.x << 7;
    int tid  = threadIdx.x;
    int lane = tid & 31;
    int wid  = tid >> 5;
    int wm   = (wid & 1) << 5;
    int wn   = (wid >> 1) << 5;

    float acc[2][4][4];
    #pragma unroll
    for (int a = 0; a < 2; a++)
        #pragma unroll
        for (int b = 0; b < 4; b++)
            #pragma unroll
            for (int j = 0; j < 4; j++) acc[a][b][j] = 0.f;

    const int la_m  = tid >> 2;
    const int la_k2 = (tid & 3) << 2;
    const int lb_k2 = tid >> 4;
    const int lb_n  = (tid & 15) << 3;

    uint4 ra[2], rb[4];
    const int nk = K >> 5;

    auto LOAD = [&](int kh) {
        const uint4* pa = (const uint4*)(A + (size_t)(m0 + la_m) * ldaH + (kh + la_k2));
        ra[0] = pa[0]; ra[1] = pa[1];
        const uint4* pb = (const uint4*)(Bw + (size_t)(kh + lb_k2) * N + (n0 + lb_n));
        rb[0] = pb[0]; rb[1] = pb[1]; rb[2] = pb[2]; rb[3] = pb[3];
    };
    auto STORE = [&](int s) {
        uint2* As = smbuf + s * STG64;
        uint2* Bs = As + K2L * PA64;
        As[(la_k2 + 0) * PA64 + la_m] = make_uint2(ra[0].x, ra[0].y);
        As[(la_k2 + 1) * PA64 + la_m] = make_uint2(ra[0].z, ra[0].w);
        As[(la_k2 + 2) * PA64 + la_m] = make_uint2(ra[1].x, ra[1].y);
        As[(la_k2 + 3) * PA64 + la_m] = make_uint2(ra[1].z, ra[1].w);
        uint4* bp4 = (uint4*)&Bs[lb_k2 * P2 + lb_n];
        bp4[0] = rb[0]; bp4[1] = rb[1]; bp4[2] = rb[2]; bp4[3] = rb[3];
    };

    LOAD(0);
    STORE(0);
    __syncthreads();

    for (int t = 0; t < nk; t++) {
        if (t + 1 < nk) LOAD((t + 1) << 4);

        const uint2* As = smbuf + (t & 1) * STG64;
        const uint2* Bs = As + K2L * PA64;

        #pragma unroll
        for (int kh = 0; kh < 2; kh++) {
            int k2q = (kh << 3) + (lane & 3);
            int qd  = lane >> 2;
            uint2 aA[2][4];
            #pragma unroll
            for (int mt = 0; mt < 2; mt++) {
                int r = wm + (mt << 4) + qd;
                aA[mt][0] = As[ k2q      * PA64 + r];
                aA[mt][1] = As[ k2q      * PA64 + r + 8];
                aA[mt][2] = As[(k2q + 4) * PA64 + r];
                aA[mt][3] = As[(k2q + 4) * PA64 + r + 8];
            }
            uint2 bB[4][2];
            #pragma unroll
            for (int nt = 0; nt < 4; nt++) {
                int cn = wn + (nt << 3) + qd;
                bB[nt][0] = Bs[ k2q      * P2 + cn];
                bB[nt][1] = Bs[(k2q + 4) * P2 + cn];
            }
            #pragma unroll
            for (int mt = 0; mt < 2; mt++) {
                unsigned ah[4] = {aA[mt][0].x, aA[mt][1].x, aA[mt][2].x, aA[mt][3].x};
                unsigned al[4] = {aA[mt][0].y, aA[mt][1].y, aA[mt][2].y, aA[mt][3].y};
                #pragma unroll
                for (int nt = 0; nt < 4; nt++) {
                    mma_bf16(acc[mt][nt], ah, bB[nt][0].x, bB[nt][1].x);
                    mma_bf16(acc[mt][nt], ah, bB[nt][0].y, bB[nt][1].y);
                    mma_bf16(acc[mt][nt], al, bB[nt][0].x, bB[nt][1].x);
                }
            }
        }

        if (t + 1 < nk) STORE((t + 1) & 1);
        __syncthreads();
    }

    #pragma unroll
    for (int mt = 0; mt < 2; mt++) {
        #pragma unroll
        for (int nt = 0; nt < 4; nt++) {
            int row = m0 + wm + (mt << 4) + (lane >> 2);
            int col = n0 + wn + (nt << 3) + ((lane & 3) << 1);
            float v[4];
            #pragma unroll
            for (int j = 0; j < 4; j++) {
                int r = row + ((j & 2) ? 8 : 0);
                int c = col + (j & 1);
                v[j] = acc[mt][nt][j] + bias[c] + resid[(size_t)r * N + c];
            }
            *(float2*)&Cp[(size_t)row * N + col]       = make_float2(v[0], v[1]);
            *(float2*)&Cp[(size_t)(row + 8) * N + col] = make_float2(v[2], v[3]);
        }
    }
}

// ---------------------------------------------------------------------------
// Fused flash attention. One CTA = (b,h) x 128 queries. 256 threads, 8 warps,
// each warp 16 query rows x full HS=64. Loop over 64-key blocks (causal).
// S = QK^T (3-term), online softmax in registers (quad shuffles), P*V with
// P A-fragments built directly from S accumulators. Output PP uint2.
// ---------------------------------------------------------------------------
__global__ void __launch_bounds__(256, 2)
fused_attn(const unsigned* __restrict__ qkv, uint2* __restrict__ o2, float scale)
{
    extern __shared__ uint2 sm[];
    uint2* Qs = sm;                 // [32 k2][132]
    uint2* Ks = Qs + FA_QS;         // [32 k2][68]   (k = HS, n = key)
    uint2* Vs = Ks + FA_KS;         // [32 key2][68] (k = key, n = HS)

    int bz = blockIdx.z;
    const unsigned* Qp = qkv + (size_t)(bz / H_) * T_ * C3_ + (size_t)(bz % H_) * HS_;
    const unsigned* Kp = Qp + C_;
    const unsigned* Vp = Qp + 2 * C_;
    uint2* Cq = o2 + (size_t)(bz / H_) * T_ * (C_ / 2) + (size_t)(bz % H_) * (HS_ / 2);

    int m0   = (int)(gridDim.y - 1 - blockIdx.y) << 7;   // heavy blocks first
    int tid  = threadIdx.x;
    int lane = tid & 31;
    int wid  = tid >> 5;
    int wm   = wid << 4;
    int qd   = lane >> 2;
    int lq   = lane & 3;

    // ---- stage Q tile (128 x 64), split+packed [k2][query] ----
    {
        int qr = tid >> 1;
        int c0 = (tid & 1) << 5;        // 0 or 32 (u32 elem index)
        const uint4* p = (const uint4*)(Qp + (size_t)(m0 + qr) * C3_ + c0);
        #pragma unroll
        for (int j = 0; j < 8; j++) {
            uint4 v = p[j];
            Qs[(c0 / 2 + 2 * j    ) * 132 + qr] = make_uint2(HIPAIR(v.x, v.y), LOPAIR(v.x, v.y));
            Qs[(c0 / 2 + 2 * j + 1) * 132 + qr] = make_uint2(HIPAIR(v.z, v.w), LOPAIR(v.z, v.w));
        }
    }

    float accO[8][4];
    #pragma unroll
    for (int n = 0; n < 8; n++)
        #pragma unroll
        for (int j = 0; j < 4; j++) accO[n][j] = 0.f;
    float m_r[2] = {-3.0e38f, -3.0e38f};
    float l_r[2] = {0.f, 0.f};

    const int nb = (m0 + 128) >> 6;

    // K staging: kr = key row (tid>>2), c0 = HS u32 index (tid&3)*16, 4 uint4
    // V staging: vk = key-pair (tid>>5), vn = HS col (tid&31)*2, 4 j-blocks
    uint4 rk[4]; uint2 rv0[4], rv1[4];
    auto LOADKV = [&](int key0) {
        int kr = tid >> 2, c0 = (tid & 3) << 4;
        const uint4* p = (const uint4*)(Kp + (size_t)(key0 + kr) * C3_ + c0);
        rk[0] = p[0]; rk[1] = p[1]; rk[2] = p[2]; rk[3] = p[3];
        int vn = (tid & 31) << 1, vk = tid >> 5;
        #pragma unroll
        for (int j = 0; j < 4; j++) {
            int k2v = vk + (j << 3);
            rv0[j] = *(const uint2*)(Vp + (size_t)(key0 + 2 * k2v    ) * C3_ + vn);
            rv1[j] = *(const uint2*)(Vp + (size_t)(key0 + 2 * k2v + 1) * C3_ + vn);
        }
    };
    auto STOREKV = [&]() {
        int kr = tid >> 2, c0 = (tid & 3) << 4;
        #pragma unroll
        for (int j = 0; j < 4; j++) {
            Ks[(c0 / 2 + 2 * j    ) * 68 + kr] = make_uint2(HIPAIR(rk[j].x, rk[j].y), LOPAIR(rk[j].x, rk[j].y));
            Ks[(c0 / 2 + 2 * j + 1) * 68 + kr] = make_uint2(HIPAIR(rk[j].z, rk[j].w), LOPAIR(rk[j].z, rk[j].w));
        }
        int vn = (tid & 31) << 1, vk = tid >> 5;
        #pragma unroll
        for (int j = 0; j < 4; j++) {
            int k2v = vk + (j << 3);
            Vs[k2v * 68 + vn    ] = make_uint2(HIPAIR(rv0[j].x, rv1[j].x), LOPAIR(rv0[j].x, rv1[j].x));
            Vs[k2v * 68 + vn + 1] = make_uint2(HIPAIR(rv0[j].y, rv1[j].y), LOPAIR(rv0[j].y, rv1[j].y));
        }
    };

    LOADKV(0);
    STOREKV();
    __syncthreads();

    for (int jb = 0; jb < nb; jb++) {
        int key0 = jb << 6;
        if (jb + 1 < nb) LOADKV((jb + 1) << 6);

        if (key0 <= m0 + wm + 15) {     // warp has at least one valid row
            // ---- S = Q K^T (16 x 64), 3-term ----
            float S[8][4];
            #pragma unroll
            for (int n = 0; n < 8; n++)
                #pragma unroll
                for (int j = 0; j < 4; j++) S[n][j] = 0.f;
            #pragma unroll
            for (int kc = 0; kc < 4; kc++) {
                int k2 = (kc << 3) + lq;
                uint2 q0 = Qs[ k2      * 132 + wm + qd];
                uint2 q1 = Qs[ k2      * 132 + wm + qd + 8];
                uint2 q2 = Qs[(k2 + 4) * 132 + wm + qd];
                uint2 q3 = Qs[(k2 + 4) * 132 + wm + qd + 8];
                unsigned qh[4] = {q0.x, q1.x, q2.x, q3.x};
                unsigned ql[4] = {q0.y, q1.y, q2.y, q3.y};
                #pragma unroll
                for (int nt = 0; nt < 8; nt++) {
                    int cn = (nt << 3) + qd;
                    uint2 b0 = Ks[ k2      * 68 + cn];
                    uint2 b1 = Ks[(k2 + 4) * 68 + cn];
                    mma_bf16(S[nt], qh, b0.x, b1.x);
                    mma_bf16(S[nt], qh, b0.y, b1.y);
                    mma_bf16(S[nt], ql, b0.x, b1.x);
                }
            }
            // ---- scale + causal mask ----
            int row0 = m0 + wm + qd, row1 = row0 + 8;
            if (key0 >= m0) {           // only last two blocks touch diagonal
                #pragma unroll
                for (int nt = 0; nt < 8; nt++) {
                    int c = key0 + (nt << 3) + (lq << 1);
                    S[nt][0] = (c     <= row0) ? S[nt][0] * scale : -3.0e38f;
                    S[nt][1] = (c + 1 <= row0) ? S[nt][1] * scale : -3.0e38f;
                    S[nt][2] = (c     <= row1) ? S[nt][2] * scale : -3.0e38f;
                    S[nt][3] = (c + 1 <= row1) ? S[nt][3] * scale : -3.0e38f;
                }
            } else {
                #pragma unroll
                for (int nt = 0; nt < 8; nt++)
                    #pragma unroll
                    for (int j = 0; j < 4; j++) S[nt][j] *= scale;
            }
            // ---- online softmax ----
            float mx0 = -3.0e38f, mx1 = -3.0e38f;
            #pragma unroll
            for (int nt = 0; nt < 8; nt++) {
                mx0 = fmaxf(mx0, fmaxf(S[nt][0], S[nt][1]));
                mx1 = fmaxf(mx1, fmaxf(S[nt][2], S[nt][3]));
            }
            mx0 = fmaxf(mx0, __shfl_xor_sync(0xffffffffu, mx0, 1));
            mx0 = fmaxf(mx0, __shfl_xor_sync(0xffffffffu, mx0, 2));
            mx1 = fmaxf(mx1, __shfl_xor_sync(0xffffffffu, mx1, 1));
            mx1 = fmaxf(mx1, __shfl_xor_sync(0xffffffffu, mx1, 2));
            float mn0 = fmaxf(m_r[0], mx0), mn1 = fmaxf(m_r[1], mx1);
            float al0 = __expf(m_r[0] - mn0), al1 = __expf(m_r[1] - mn1);
            m_r[0] = mn0; m_r[1] = mn1;
            float s0 = 0.f, s1 = 0.f;
            #pragma unroll
            for (int nt = 0; nt < 8; nt++) {
                S[nt][0] = __expf(S[nt][0] - mn0);
                S[nt][1] = __expf(S[nt][1] - mn0);
                S[nt][2] = __expf(S[nt][2] - mn1);
                S[nt][3] = __expf(S[nt][3] - mn1);
                s0 += S[nt][0] + S[nt][1];
                s1 += S[nt][2] + S[nt][3];
            }
            s0 += __shfl_xor_sync(0xffffffffu, s0, 1);
            s0 += __shfl_xor_sync(0xffffffffu, s0, 2);
            s1 += __shfl_xor_sync(0xffffffffu, s1, 1);
            s1 += __shfl_xor_sync(0xffffffffu, s1, 2);
            l_r[0] = l_r[0] * al0 + s0;
            l_r[1] = l_r[1] * al1 + s1;
            #pragma unroll
            for (int nt = 0; nt < 8; nt++) {
                accO[nt][0] *= al0; accO[nt][1] *= al0;
                accO[nt][2] *= al1; accO[nt][3] *= al1;
            }
            // ---- O += P V (P A-fragments from S accumulators) ----
            #pragma unroll
            for (int kc = 0; kc < 4; kc++) {
                uint2 u01 = packpair(S[2*kc    ][0], S[2*kc    ][1]);
                uint2 u23 = packpair(S[2*kc    ][2], S[2*kc    ][3]);
                uint2 u45 = packpair(S[2*kc + 1][0], S[2*kc + 1][1]);
                uint2 u67 = packpair(S[2*kc + 1][2], S[2*kc + 1][3]);
                unsigned ph[4] = {u01.x, u23.x, u45.x, u67.x};
                unsigned pl[4] = {u01.y, u23.y, u45.y, u67.y};
                int k2 = (kc << 3) + lq;
                #pragma unroll
                for (int nt = 0; nt < 8; nt++) {
                    int cn = (nt << 3) + qd;
                    uint2 b0 = Vs[ k2      * 68 + cn];
                    uint2 b1 = Vs[(k2 + 4) * 68 + cn];
                    mma_bf16(accO[nt], ph, b0.x, b1.x);
                    mma_bf16(accO[nt], ph, b0.y, b1.y);
                    mma_bf16(accO[nt], pl, b0.x, b1.x);
                }
            }
        }

        __syncthreads();
        if (jb + 1 < nb) {
            STOREKV();
            __syncthreads();
        }
    }

    // ---- epilogue: normalize and write PP ----
    float inv0 = 1.f / l_r[0], inv1 = 1.f / l_r[1];
    int row = m0 + wm + qd;
    #pragma unroll
    for (int nt = 0; nt < 8; nt++) {
        int col = (nt << 3) + (lq << 1);
        Cq[(size_t)row * (C_ / 2) + (col >> 1)] =
            packpair(accO[nt][0] * inv0, accO[nt][1] * inv0);
        Cq[(size_t)(row + 8) * (C_ / 2) + (col >> 1)] =
            packpair(accO[nt][2] * inv1, accO[nt][3] * inv1);
    }
}

// ---------------------------------------------------------------------------
// Weight pre-pack: src rows paired -> PP [rows/2][N] uint2
// ---------------------------------------------------------------------------
__global__ void pack_w(const float* __restrict__ src, uint2* __restrict__ dst,
                       int halfRows, int N)
{
    int i = blockIdx.x * 256 + threadIdx.x;
    if (i < halfRows * N) {
        int g = i / N, j = i - g * N;
        dst[i] = packpair(src[(size_t)(2 * g) * N + j],
                          src[(size_t)(2 * g + 1) * N + j]);
    }
}

// Pack Wq/Wk/Wv [L][C][C] -> PP Wcat [L][C/2][3C]
__global__ void pack_qkv_pp(const float* __restrict__ Wq, const float* __restrict__ Wk,
                            const float* __restrict__ Wv, uint2* __restrict__ Wcat)
{
    int i = blockIdx.x * 256 + threadIdx.x;
    if (i < L_ * (C_ / 2) * C_) {
        int l  = i / ((C_ / 2) * C_);
        int rm = i - l * ((C_ / 2) * C_);
        int k2 = rm / C_, j = rm - k2 * C_;
        size_t so = (size_t)l * C_ * C_;
        uint2* W = Wcat + (size_t)l * (C_ / 2) * C3_ + (size_t)k2 * C3_;
        W[j]          = packpair(Wq[so + (size_t)(2*k2) * C_ + j], Wq[so + (size_t)(2*k2+1) * C_ + j]);
        W[C_ + j]     = packpair(Wk[so + (size_t)(2*k2) * C_ + j], Wk[so + (size_t)(2*k2+1) * C_ + j]);
        W[2 * C_ + j] = packpair(Wv[so + (size_t)(2*k2) * C_ + j], Wv[so + (size_t)(2*k2+1) * C_ + j]);
    }
}

// ---------------------------------------------------------------------------
// LayerNorm (biased variance, eps=1e-5) -> PP uint2 output
// ---------------------------------------------------------------------------
__global__ void layernorm_pp(const float* __restrict__ x, const float* __restrict__ g,
                             const float* __restrict__ b, uint2* __restrict__ y)
{
    int row = blockIdx.x;
    const float* xr = x + (size_t)row * C_;
    uint2* yr       = y + (size_t)row * (C_ / 2);
    int tid = threadIdx.x;
    float s = 0.f, s2 = 0.f;
    for (int c = tid; c < C_; c += 256) { float v = xr[c]; s += v; s2 += v * v; }
    __shared__ float shs[8], shs2[8];
    #pragma unroll
    for (int o = 16; o; o >>= 1) {
        s  += __shfl_xor_sync(0xffffffffu, s,  o);
        s2 += __shfl_xor_sync(0xffffffffu, s2, o);
    }
    if ((tid & 31) == 0) { shs[tid >> 5] = s; shs2[tid >> 5] = s2; }
    __syncthreads();
    float ts = 0.f, ts2 = 0.f;
    #pragma unroll
    for (int i = 0; i < 8; i++) { ts += shs[i]; ts2 += shs2[i]; }
    float mean = ts * (1.f / C_);
    float var  = ts2 * (1.f / C_) - mean * mean;
    float rstd = rsqrtf(var + 1e-5f);
    for (int p = tid; p < C_ / 2; p += 256) {
        float2 xv = ((const float2*)xr)[p];
        float2 gv = ((const float2*)g)[p];
        float2 bv = ((const float2*)b)[p];
        yr[p] = packpair((xv.x - mean) * rstd * gv.x + bv.x,
                         (xv.y - mean) * rstd * gv.y + bv.y);
    }
}

// ---------------------------------------------------------------------------
// Embedding
// ---------------------------------------------------------------------------
__global__ void embed_k(const int* __restrict__ idx, const float* __restrict__ tok,
                        const float* __restrict__ pos, float* __restrict__ x)
{
    int r = blockIdx.x;
    int t = r & (T_ - 1);
    int token = idx[r];
    const float* te = tok + (size_t)token * C_;
    const float* pe = pos + (size_t)t * C_;
    float* xr = x + (size_t)r * C_;
    for (int c = threadIdx.x; c < C_; c += 256) xr[c] = te[c] + pe[c];
}

// ---------------------------------------------------------------------------
// Launch
// ---------------------------------------------------------------------------
extern "C" void kernel_launch(void* const* d_in, const int* in_sizes, int n_in,
                              void* d_out, int out_size)
{
    (void)in_sizes; (void)n_in; (void)out_size;
    const int*   idx = (const int*)d_in[0];
    const float* tok = (const float*)d_in[1];
    const float* pos = (const float*)d_in[2];
    const float* Wq  = (const float*)d_in[3];
    const float* Wk  = (const float*)d_in[4];
    const float* Wv  = (const float*)d_in[5];
    const float* Wp  = (const float*)d_in[6];
    const float* bp  = (const float*)d_in[7];
    const float* g1  = (const float*)d_in[8];
    const float* be1 = (const float*)d_in[9];
    const float* g2  = (const float*)d_in[10];
    const float* be2 = (const float*)d_in[11];
    const float* W1  = (const float*)d_in[12];
    const float* bb1 = (const float*)d_in[13];
    const float* W2  = (const float*)d_in[14];
    const float* bb2 = (const float*)d_in[15];
    const float* gf  = (const float*)d_in[16];
    const float* bf  = (const float*)d_in[17];
    const float* Wh  = (const float*)d_in[18];
    const float* bhd = (const float*)d_in[19];
    float* out = (float*)d_out;

    float    *x;
    unsigned *qkv2;
    uint2    *h2, *o2, *a12, *wcat2, *wp2, *w12, *w22, *wh2;
    cudaGetSymbolAddress((void**)&x,     g_x);
    cudaGetSymbolAddress((void**)&h2,    g_h2);
    cudaGetSymbolAddress((void**)&qkv2,  g_qkv2);
    cudaGetSymbolAddress((void**)&o2,    g_o2);
    cudaGetSymbolAddress((void**)&a12,   g_a12);
    cudaGetSymbolAddress((void**)&wcat2, g_wcat2);
    cudaGetSymbolAddress((void**)&wp2,   g_wp2);
    cudaGetSymbolAddress((void**)&w12,   g_w12);
    cudaGetSymbolAddress((void**)&w22,   g_w22);
    cudaGetSymbolAddress((void**)&wh2,   g_wh2);

    cudaFuncSetAttribute((const void*)gemm_lin,
                         cudaFuncAttributeMaxDynamicSharedMemorySize, (int)SMEM_LIN);
    cudaFuncSetAttribute((const void*)gemm_lin64,
                         cudaFuncAttributeMaxDynamicSharedMemorySize, (int)SMEM_L64);
    cudaFuncSetAttribute((const void*)fused_attn,
                         cudaFuncAttributeMaxDynamicSharedMemorySize, (int)SMEM_FA);

    const float att_scale = 0.03608439182435161f;  // 768^-0.5 (reference uses full C)
    const float* NOF = (const float*)0;

    embed_k<<<BT_, 256>>>(idx, tok, pos, x);

    // --- pre-split + pre-pack all weights (batched over layers) ---
    pack_qkv_pp<<<(L_ * (C_ / 2) * C_ + 255) / 256, 256>>>(Wq, Wk, Wv, wcat2);
    pack_w<<<(L_ * (C_ / 2) * C_  + 255) / 256, 256>>>(Wp, wp2, L_ * C_ / 2, C_);
    pack_w<<<(L_ * (C_ / 2) * C4_ + 255) / 256, 256>>>(W1, w12, L_ * C_ / 2, C4_);
    pack_w<<<(L_ * (C4_ / 2) * C_ + 255) / 256, 256>>>(W2, w22, L_ * C4_ / 2, C_);
    pack_w<<<((C_ / 2) * V_ + 255) / 256, 256>>>(Wh, wh2, C_ / 2, V_);

    dim3 gqkv(C3_ / 128, BT_ / 128, 1);
    dim3 gc64(C_  / 128, BT_ / 64,  1);
    dim3 gfa (1,         T_  / 128, B_ * H_);
    dim3 gf1 (C4_ / 128, BT_ / 128, 1);

    for (int l = 0; l < L_; l++) {
        layernorm_pp<<<BT_, 256>>>(x, g1 + l * C_, be1 + l * C_, h2);

        // qkv = h @ Wcat -> EW u32 [BT][3C]
        gemm_lin<<<gqkv, 512, SMEM_LIN>>>(h2, wcat2 + (size_t)l * (C_/2) * C3_,
                (float*)qkv2, BT_, C3_, C_, NOF, NOF, 0, 1);

        // fused flash attention -> o (PP)
        fused_attn<<<gfa, 256, SMEM_FA>>>(qkv2, o2, att_scale);

        // x = x + o @ Wproj + bproj
        gemm_lin64<<<gc64, 256, SMEM_L64>>>(o2, wp2 + (size_t)l * (C_/2) * C_,
                x, C_, C_, bp + l * C_, x);

        layernorm_pp<<<BT_, 256>>>(x, g2 + l * C_, be2 + l * C_, h2);

        // a1 = gelu(h @ W1 + b1) -> PP
        gemm_lin<<<gf1, 512, SMEM_LIN>>>(h2, w12 + (size_t)l * (C_/2) * C4_,
                (float*)a12, BT_, C4_, C_, bb1 + l * C4_, NOF, 1, 2);

        // x = x + a1 @ W2 + b2
        gemm_lin64<<<gc64, 256, SMEM_L64>>>(a12, w22 + (size_t)l * (C4_/2) * C_,
                x, C_, C4_, bb2 + l * C_, x);
    }

    layernorm_pp<<<BT_, 256>>>(x, gf, bf, h2);

    // head: 3-term bf16
    dim3 ghd(V_ / 128, BT_ / 128, 1);
    gemm_lin<<<ghd, 512, SMEM_LIN>>>(h2, wh2, out, BT_, V_, C_, bhd, NOF, 0, 0);
}

// round 17
// speedup vs baseline: 1.4202x; 1.4202x over previous
#include <cuda_runtime.h>
#include <cuda_bf16.h>
#include <math.h>

// ---------------------------------------------------------------------------
// GPT-2 small forward. fp32 activations; GEMMs use split-bf16 (3xBF16)
// mma.sync.m16n8k16 on pre-split, pre-packed k-pair planar uint2 operands.
// Linear GEMMs: KT=32 double-buffered, 512-thr 128x128 tiles; a 256-thr
// 64x128 variant (2 CTAs/SM) for the proj/fc2 launches. Unfused attention
// (scores GEMM + causal softmax + AV GEMM) — the R14 configuration, with
// __expf softmax and vectorized weight packing.
// ---------------------------------------------------------------------------

namespace {
constexpr int B_  = 4;
constexpr int T_  = 1024;
constexpr int C_  = 768;
constexpr int H_  = 12;
constexpr int HS_ = 64;
constexpr int L_  = 12;
constexpr int V_  = 32000;
constexpr int BT_ = B_ * T_;
constexpr int C4_ = 4 * C_;
constexpr int C3_ = 3 * C_;

constexpr int P2  = 132;                // B smem row pitch in uint2

// attention kernels (KT=16)
constexpr int K2T   = 8;
constexpr int STG2  = 2 * K2T * P2;
constexpr size_t SMEM_SA = 2 * STG2 * sizeof(uint2);      // 33792 B

// linear GEMM 128x128 (KT=32)
constexpr int K2L   = 16;
constexpr int STGL  = 2 * K2L * P2;
constexpr size_t SMEM_LIN = 2 * STGL * sizeof(uint2);     // 67584 B

// linear GEMM 64x128 (KT=32), A-pitch 68
constexpr int PA64  = 68;
constexpr int STG64 = K2L * PA64 + K2L * P2;
constexpr size_t SMEM_L64 = 2 * STG64 * sizeof(uint2);    // 51200 B
}

// Scratch (no cudaMalloc -> device globals)
__device__ float    g_x   [BT_ * C_];
__device__ uint2    g_h2  [BT_ * C_ / 2];      // PP: [row][C/2]
__device__ unsigned g_qkv2[BT_ * C3_];         // EW u32 per element
__device__ uint2    g_o2  [BT_ * C_ / 2];      // PP
__device__ uint2    g_a12 [BT_ * C4_ / 2];     // PP
__device__ float    g_att [(size_t)B_ * H_ * T_ * T_];
// all-layer pre-split packed weights: [k2][n] uint2
__device__ uint2 g_wcat2[(size_t)L_ * (C_ / 2) * C3_];
__device__ uint2 g_wp2  [(size_t)L_ * (C_ / 2) * C_];
__device__ uint2 g_w12  [(size_t)L_ * (C_ / 2) * C4_];
__device__ uint2 g_w22  [(size_t)L_ * (C4_ / 2) * C_];
__device__ uint2 g_wh2  [(size_t)(C_ / 2) * V_];

// ---------------------------------------------------------------------------
// bf16 split helpers
// ---------------------------------------------------------------------------
__device__ __forceinline__ unsigned splitbf(float x) {
    __nv_bfloat16 h = __float2bfloat16(x);
    float hf = __bfloat162float(h);
    __nv_bfloat16 l = __float2bfloat16(x - hf);
    return (unsigned)__bfloat16_as_ushort(h) |
           ((unsigned)__bfloat16_as_ushort(l) << 16);
}

#define HIPAIR(e0, e1) __byte_perm((e0), (e1), 0x5410)
#define LOPAIR(e0, e1) __byte_perm((e0), (e1), 0x7632)

__device__ __forceinline__ uint2 packpair(float a, float b) {
    unsigned u0 = splitbf(a), u1 = splitbf(b);
    return make_uint2(HIPAIR(u0, u1), LOPAIR(u0, u1));
}

__device__ __forceinline__ void mma_bf16(float* d, const unsigned* a,
                                         unsigned b0, unsigned b1) {
    asm volatile(
        "mma.sync.aligned.m16n8k16.row.col.f32.bf16.bf16.f32 "
        "{%0,%1,%2,%3}, {%4,%5,%6,%7}, {%8,%9}, {%0,%1,%2,%3};"
        : "+f"(d[0]), "+f"(d[1]), "+f"(d[2]), "+f"(d[3])
        : "r"(a[0]), "r"(a[1]), "r"(a[2]), "r"(a[3]),
          "r"(b0), "r"(b1));
}

// ---------------------------------------------------------------------------
// Linear GEMM 128x128, KT=32, 512 threads, 16 warps (4x4), warp tile 32x32.
// A: PP [M][K/2] uint2.  B: PP [K/2][N] uint2.
// outMode: 0 plain float, 1 EW u32, 2 PP uint2.
// ---------------------------------------------------------------------------
__global__ void __launch_bounds__(512)
gemm_lin(const uint2* __restrict__ A, const uint2* __restrict__ Bw,
         float* __restrict__ Cp, int M, int N, int K,
         const float* __restrict__ bias, const float* __restrict__ resid,
         int doGelu, int outMode)
{
    extern __shared__ uint2 smbuf[];
    const int ldaH = K >> 1;

    int m0   = blockIdx.y << 7;
    int n0   = blockIdx.x << 7;
    int tid  = threadIdx.x;
    int lane = tid & 31;
    int wid  = tid >> 5;
    int wm   = (wid & 3) << 5;
    int wn   = (wid >> 2) << 5;

    float acc[2][4][4];
    #pragma unroll
    for (int a = 0; a < 2; a++)
        #pragma unroll
        for (int b = 0; b < 4; b++)
            #pragma unroll
            for (int j = 0; j < 4; j++) acc[a][b][j] = 0.f;

    const int la_m  = tid >> 2;
    const int la_k2 = (tid & 3) << 2;
    const int lb_k2 = tid >> 5;
    const int lb_n  = (tid & 31) << 2;

    uint4 ra[2], rb[2];
    const int nk = K >> 5;

    auto LOAD = [&](int kh) {
        const uint4* pa = (const uint4*)(A + (size_t)(m0 + la_m) * ldaH + (kh + la_k2));
        ra[0] = pa[0]; ra[1] = pa[1];
        const uint4* pb = (const uint4*)(Bw + (size_t)(kh + lb_k2) * N + (n0 + lb_n));
        rb[0] = pb[0]; rb[1] = pb[1];
    };
    auto STORE = [&](int s) {
        uint2* As = smbuf + s * STGL;
        uint2* Bs = As + K2L * P2;
        As[(la_k2 + 0) * P2 + la_m] = make_uint2(ra[0].x, ra[0].y);
        As[(la_k2 + 1) * P2 + la_m] = make_uint2(ra[0].z, ra[0].w);
        As[(la_k2 + 2) * P2 + la_m] = make_uint2(ra[1].x, ra[1].y);
        As[(la_k2 + 3) * P2 + la_m] = make_uint2(ra[1].z, ra[1].w);
        *(uint4*)&Bs[lb_k2 * P2 + lb_n]     = rb[0];
        *(uint4*)&Bs[lb_k2 * P2 + lb_n + 2] = rb[1];
    };

    LOAD(0);
    STORE(0);
    __syncthreads();

    for (int t = 0; t < nk; t++) {
        if (t + 1 < nk) LOAD((t + 1) << 4);

        const uint2* As = smbuf + (t & 1) * STGL;
        const uint2* Bs = As + K2L * P2;

        #pragma unroll
        for (int kh = 0; kh < 2; kh++) {
            int k2q = (kh << 3) + (lane & 3);
            int qd  = lane >> 2;
            uint2 aA[2][4];
            #pragma unroll
            for (int mt = 0; mt < 2; mt++) {
                int r = wm + (mt << 4) + qd;
                aA[mt][0] = As[ k2q      * P2 + r];
                aA[mt][1] = As[ k2q      * P2 + r + 8];
                aA[mt][2] = As[(k2q + 4) * P2 + r];
                aA[mt][3] = As[(k2q + 4) * P2 + r + 8];
            }
            uint2 bB[4][2];
            #pragma unroll
            for (int nt = 0; nt < 4; nt++) {
                int cn = wn + (nt << 3) + qd;
                bB[nt][0] = Bs[ k2q      * P2 + cn];
                bB[nt][1] = Bs[(k2q + 4) * P2 + cn];
            }
            #pragma unroll
            for (int mt = 0; mt < 2; mt++) {
                unsigned ah[4] = {aA[mt][0].x, aA[mt][1].x, aA[mt][2].x, aA[mt][3].x};
                unsigned al[4] = {aA[mt][0].y, aA[mt][1].y, aA[mt][2].y, aA[mt][3].y};
                #pragma unroll
                for (int nt = 0; nt < 4; nt++) {
                    mma_bf16(acc[mt][nt], ah, bB[nt][0].x, bB[nt][1].x);
                    mma_bf16(acc[mt][nt], ah, bB[nt][0].y, bB[nt][1].y);
                    mma_bf16(acc[mt][nt], al, bB[nt][0].x, bB[nt][1].x);
                }
            }
        }

        if (t + 1 < nk) STORE((t + 1) & 1);
        __syncthreads();
    }

    unsigned* Cu = (unsigned*)Cp;
    uint2*    Cq = (uint2*)Cp;
    #pragma unroll
    for (int mt = 0; mt < 2; mt++) {
        #pragma unroll
        for (int nt = 0; nt < 4; nt++) {
            int row = m0 + wm + (mt << 4) + (lane >> 2);
            int col = n0 + wn + (nt << 3) + ((lane & 3) << 1);
            float v[4];
            #pragma unroll
            for (int j = 0; j < 4; j++) {
                int r = row + ((j & 2) ? 8 : 0);
                int c = col + (j & 1);
                float vv = acc[mt][nt][j];
                if (bias) vv += bias[c];
                if (doGelu) vv = 0.5f * vv * (1.f + erff(vv * 0.70710678118654752f));
                if (resid) vv += resid[(size_t)r * N + c];
                v[j] = vv;
            }
            if (outMode == 0) {
                *(float2*)&Cp[(size_t)row * N + col]       = make_float2(v[0], v[1]);
                *(float2*)&Cp[(size_t)(row + 8) * N + col] = make_float2(v[2], v[3]);
            } else if (outMode == 1) {
                Cu[(size_t)row * N + col]           = splitbf(v[0]);
                Cu[(size_t)row * N + col + 1]       = splitbf(v[1]);
                Cu[(size_t)(row + 8) * N + col]     = splitbf(v[2]);
                Cu[(size_t)(row + 8) * N + col + 1] = splitbf(v[3]);
            } else {
                Cq[(size_t)row * (N >> 1) + (col >> 1)]       = packpair(v[0], v[1]);
                Cq[(size_t)(row + 8) * (N >> 1) + (col >> 1)] = packpair(v[2], v[3]);
            }
        }
    }
}

// ---------------------------------------------------------------------------
// Linear GEMM 64x128, KT=32, 256 threads, 8 warps (2x4). 2 CTAs/SM.
// Plain-float output with bias+resid (proj and fc2).
// ---------------------------------------------------------------------------
__global__ void __launch_bounds__(256, 2)
gemm_lin64(const uint2* __restrict__ A, const uint2* __restrict__ Bw,
           float* __restrict__ Cp, int N, int K,
           const float* __restrict__ bias, const float* __restrict__ resid)
{
    extern __shared__ uint2 smbuf[];
    const int ldaH = K >> 1;

    int m0   = blockIdx.y << 6;
    int n0   = blockIdx.x << 7;
    int tid  = threadIdx.x;
    int lane = tid & 31;
    int wid  = tid >> 5;
    int wm   = (wid & 1) << 5;
    int wn   = (wid >> 1) << 5;

    float acc[2][4][4];
    #pragma unroll
    for (int a = 0; a < 2; a++)
        #pragma unroll
        for (int b = 0; b < 4; b++)
            #pragma unroll
            for (int j = 0; j < 4; j++) acc[a][b][j] = 0.f;

    const int la_m  = tid >> 2;
    const int la_k2 = (tid & 3) << 2;
    const int lb_k2 = tid >> 4;
    const int lb_n  = (tid & 15) << 3;

    uint4 ra[2], rb[4];
    const int nk = K >> 5;

    auto LOAD = [&](int kh) {
        const uint4* pa = (const uint4*)(A + (size_t)(m0 + la_m) * ldaH + (kh + la_k2));
        ra[0] = pa[0]; ra[1] = pa[1];
        const uint4* pb = (const uint4*)(Bw + (size_t)(kh + lb_k2) * N + (n0 + lb_n));
        rb[0] = pb[0]; rb[1] = pb[1]; rb[2] = pb[2]; rb[3] = pb[3];
    };
    auto STORE = [&](int s) {
        uint2* As = smbuf + s * STG64;
        uint2* Bs = As + K2L * PA64;
        As[(la_k2 + 0) * PA64 + la_m] = make_uint2(ra[0].x, ra[0].y);
        As[(la_k2 + 1) * PA64 + la_m] = make_uint2(ra[0].z, ra[0].w);
        As[(la_k2 + 2) * PA64 + la_m] = make_uint2(ra[1].x, ra[1].y);
        As[(la_k2 + 3) * PA64 + la_m] = make_uint2(ra[1].z, ra[1].w);
        uint4* bp4 = (uint4*)&Bs[lb_k2 * P2 + lb_n];
        bp4[0] = rb[0]; bp4[1] = rb[1]; bp4[2] = rb[2]; bp4[3] = rb[3];
    };

    LOAD(0);
    STORE(0);
    __syncthreads();

    for (int t = 0; t < nk; t++) {
        if (t + 1 < nk) LOAD((t + 1) << 4);

        const uint2* As = smbuf + (t & 1) * STG64;
        const uint2* Bs = As + K2L * PA64;

        #pragma unroll
        for (int kh = 0; kh < 2; kh++) {
            int k2q = (kh << 3) + (lane & 3);
            int qd  = lane >> 2;
            uint2 aA[2][4];
            #pragma unroll
            for (int mt = 0; mt < 2; mt++) {
                int r = wm + (mt << 4) + qd;
                aA[mt][0] = As[ k2q      * PA64 + r];
                aA[mt][1] = As[ k2q      * PA64 + r + 8];
                aA[mt][2] = As[(k2q + 4) * PA64 + r];
                aA[mt][3] = As[(k2q + 4) * PA64 + r + 8];
            }
            uint2 bB[4][2];
            #pragma unroll
            for (int nt = 0; nt < 4; nt++) {
                int cn = wn + (nt << 3) + qd;
                bB[nt][0] = Bs[ k2q      * P2 + cn];
                bB[nt][1] = Bs[(k2q + 4) * P2 + cn];
            }
            #pragma unroll
            for (int mt = 0; mt < 2; mt++) {
                unsigned ah[4] = {aA[mt][0].x, aA[mt][1].x, aA[mt][2].x, aA[mt][3].x};
                unsigned al[4] = {aA[mt][0].y, aA[mt][1].y, aA[mt][2].y, aA[mt][3].y};
                #pragma unroll
                for (int nt = 0; nt < 4; nt++) {
                    mma_bf16(acc[mt][nt], ah, bB[nt][0].x, bB[nt][1].x);
                    mma_bf16(acc[mt][nt], ah, bB[nt][0].y, bB[nt][1].y);
                    mma_bf16(acc[mt][nt], al, bB[nt][0].x, bB[nt][1].x);
                }
            }
        }

        if (t + 1 < nk) STORE((t + 1) & 1);
        __syncthreads();
    }

    #pragma unroll
    for (int mt = 0; mt < 2; mt++) {
        #pragma unroll
        for (int nt = 0; nt < 4; nt++) {
            int row = m0 + wm + (mt << 4) + (lane >> 2);
            int col = n0 + wn + (nt << 3) + ((lane & 3) << 1);
            float v[4];
            #pragma unroll
            for (int j = 0; j < 4; j++) {
                int r = row + ((j & 2) ? 8 : 0);
                int c = col + (j & 1);
                v[j] = acc[mt][nt][j] + bias[c] + resid[(size_t)r * N + c];
            }
            *(float2*)&Cp[(size_t)row * N + col]       = make_float2(v[0], v[1]);
            *(float2*)&Cp[(size_t)(row + 8) * N + col] = make_float2(v[2], v[3]);
        }
    }
}

// ---------------------------------------------------------------------------
// Scores GEMM: att[b,h] = Q @ K^T * alpha. EW u32 operands in qkv2.
// 512 threads, tile 128x128, K=HS=64 (KT=16). Upper blocks skipped.
// ---------------------------------------------------------------------------
__global__ void __launch_bounds__(512)
gemm_sc(const unsigned* __restrict__ qkv, float* __restrict__ att, float alpha)
{
    if (blockIdx.x > blockIdx.y) return;
    extern __shared__ uint2 smbuf[];

    int bz = blockIdx.z;
    const unsigned* A  = qkv + (size_t)(bz / H_) * T_ * C3_ + (size_t)(bz % H_) * HS_;
    const unsigned* Bq = A + C_;
    float* Cb = att + (size_t)bz * T_ * T_;

    int m0   = blockIdx.y << 7;
    int n0   = blockIdx.x << 7;
    int tid  = threadIdx.x;
    int lane = tid & 31;
    int wid  = tid >> 5;
    int wm   = (wid & 3) << 5;
    int wn   = (wid >> 2) << 5;

    float acc[2][4][4];
    #pragma unroll
    for (int a = 0; a < 2; a++)
        #pragma unroll
        for (int b = 0; b < 4; b++)
            #pragma unroll
            for (int j = 0; j < 4; j++) acc[a][b][j] = 0.f;

    const int la_m = tid >> 2;
    const int la_k = (tid & 3) << 2;

    uint4 ra, rbT;
    const int nk = HS_ >> 4;

    auto LOAD = [&](int k0) {
        ra  = *(const uint4*)(A  + (size_t)(m0 + la_m) * C3_ + (k0 + la_k));
        rbT = *(const uint4*)(Bq + (size_t)(n0 + la_m) * C3_ + (k0 + la_k));
    };
    auto STORE = [&](int s) {
        uint2* As = smbuf + s * STG2;
        uint2* Bs = As + K2T * P2;
        int k2 = la_k >> 1;
        As[(k2    ) * P2 + la_m] = make_uint2(HIPAIR(ra.x, ra.y), LOPAIR(ra.x, ra.y));
        As[(k2 + 1) * P2 + la_m] = make_uint2(HIPAIR(ra.z, ra.w), LOPAIR(ra.z, ra.w));
        Bs[(k2    ) * P2 + la_m] = make_uint2(HIPAIR(rbT.x, rbT.y), LOPAIR(rbT.x, rbT.y));
        Bs[(k2 + 1) * P2 + la_m] = make_uint2(HIPAIR(rbT.z, rbT.w), LOPAIR(rbT.z, rbT.w));
    };

    LOAD(0);
    STORE(0);
    __syncthreads();

    for (int t = 0; t < nk; t++) {
        if (t + 1 < nk) LOAD((t + 1) << 4);

        const uint2* As = smbuf + (t & 1) * STG2;
        const uint2* Bs = As + K2T * P2;

        int k2q = lane & 3;
        int qd  = lane >> 2;
        uint2 aA[2][4];
        #pragma unroll
        for (int mt = 0; mt < 2; mt++) {
            int r = wm + (mt << 4) + qd;
            aA[mt][0] = As[ k2q      * P2 + r];
            aA[mt][1] = As[ k2q      * P2 + r + 8];
            aA[mt][2] = As[(k2q + 4) * P2 + r];
            aA[mt][3] = As[(k2q + 4) * P2 + r + 8];
        }
        uint2 bB[4][2];
        #pragma unroll
        for (int nt = 0; nt < 4; nt++) {
            int cn = wn + (nt << 3) + qd;
            bB[nt][0] = Bs[ k2q      * P2 + cn];
            bB[nt][1] = Bs[(k2q + 4) * P2 + cn];
        }
        #pragma unroll
        for (int mt = 0; mt < 2; mt++) {
            unsigned ah[4] = {aA[mt][0].x, aA[mt][1].x, aA[mt][2].x, aA[mt][3].x};
            unsigned al[4] = {aA[mt][0].y, aA[mt][1].y, aA[mt][2].y, aA[mt][3].y};
            #pragma unroll
            for (int nt = 0; nt < 4; nt++) {
                mma_bf16(acc[mt][nt], ah, bB[nt][0].x, bB[nt][1].x);
                mma_bf16(acc[mt][nt], ah, bB[nt][0].y, bB[nt][1].y);
                mma_bf16(acc[mt][nt], al, bB[nt][0].x, bB[nt][1].x);
            }
        }

        if (t + 1 < nk) STORE((t + 1) & 1);
        __syncthreads();
    }

    #pragma unroll
    for (int mt = 0; mt < 2; mt++) {
        #pragma unroll
        for (int nt = 0; nt < 4; nt++) {
            int row = m0 + wm + (mt << 4) + (lane >> 2);
            int col = n0 + wn + (nt << 3) + ((lane & 3) << 1);
            *(float2*)&Cb[(size_t)row * T_ + col] =
                make_float2(acc[mt][nt][0] * alpha, acc[mt][nt][1] * alpha);
            *(float2*)&Cb[(size_t)(row + 8) * T_ + col] =
                make_float2(acc[mt][nt][2] * alpha, acc[mt][nt][3] * alpha);
        }
    }
}

// ---------------------------------------------------------------------------
// AV GEMM: o[b,h] = P @ V. A = att (PP in place by softmax). B = V (EW u32,
// PRMT-packed in staging). 256 threads, 8 warps x 1, warp tile 16x64.
// K causally clamped. Out PP. KT=16.
// ---------------------------------------------------------------------------
__global__ void __launch_bounds__(256)
gemm_av(const float* __restrict__ attf, const unsigned* __restrict__ qkv,
        uint2* __restrict__ o2)
{
    extern __shared__ uint2 smbuf[];
    int bz = blockIdx.z;
    const uint2* Apk = (const uint2*)attf + (size_t)bz * T_ * (T_ / 2);
    const unsigned* Bp = qkv + (size_t)(bz / H_) * T_ * C3_ + (size_t)(bz % H_) * HS_ + 2 * C_;
    uint2* Cq = o2 + (size_t)(bz / H_) * T_ * (C_ / 2) + (size_t)(bz % H_) * (HS_ / 2);

    int m0   = blockIdx.y << 7;
    int tid  = threadIdx.x;
    int lane = tid & 31;
    int wid  = tid >> 5;
    int wm   = wid << 4;

    const int nk = (m0 + 128) >> 4;     // causal clamp

    float acc[8][4];
    #pragma unroll
    for (int b = 0; b < 8; b++)
        #pragma unroll
        for (int j = 0; j < 4; j++) acc[b][j] = 0.f;

    const int la_m  = tid >> 2;
    const int la_k2 = (tid & 3) << 1;
    const int lb_k2 = tid >> 5;
    const int lb_n  = (tid & 31) << 1;

    uint4 ra[2]; uint2 rb0, rb1;

    auto LOAD = [&](int kh) {
        #pragma unroll
        for (int j = 0; j < 2; j++) {
            int m = la_m + (j << 6);
            ra[j] = *(const uint4*)(Apk + (size_t)(m0 + m) * (T_ / 2) + (kh + la_k2));
        }
        int k0 = kh << 1;
        rb0 = *(const uint2*)(Bp + (size_t)(k0 + 2 * lb_k2)     * C3_ + lb_n);
        rb1 = *(const uint2*)(Bp + (size_t)(k0 + 2 * lb_k2 + 1) * C3_ + lb_n);
    };
    auto STORE = [&](int s) {
        uint2* As = smbuf + s * STG2;
        uint2* Bs = As + K2T * P2;
        #pragma unroll
        for (int j = 0; j < 2; j++) {
            int m = la_m + (j << 6);
            As[(la_k2    ) * P2 + m] = make_uint2(ra[j].x, ra[j].y);
            As[(la_k2 + 1) * P2 + m] = make_uint2(ra[j].z, ra[j].w);
        }
        Bs[lb_k2 * P2 + lb_n    ] = make_uint2(HIPAIR(rb0.x, rb1.x), LOPAIR(rb0.x, rb1.x));
        Bs[lb_k2 * P2 + lb_n + 1] = make_uint2(HIPAIR(rb0.y, rb1.y), LOPAIR(rb0.y, rb1.y));
    };

    LOAD(0);
    STORE(0);
    __syncthreads();

    for (int t = 0; t < nk; t++) {
        if (t + 1 < nk) LOAD((t + 1) << 3);

        const uint2* As = smbuf + (t & 1) * STG2;
        const uint2* Bs = As + K2T * P2;

        int k2q = lane & 3;
        int qd  = lane >> 2;
        int r   = wm + qd;
        uint2 a0 = As[ k2q      * P2 + r];
        uint2 a1 = As[ k2q      * P2 + r + 8];
        uint2 a2 = As[(k2q + 4) * P2 + r];
        uint2 a3 = As[(k2q + 4) * P2 + r + 8];
        unsigned ah[4] = {a0.x, a1.x, a2.x, a3.x};
        unsigned al[4] = {a0.y, a1.y, a2.y, a3.y};
        #pragma unroll
        for (int nt = 0; nt < 8; nt++) {
            int cn = (nt << 3) + qd;
            uint2 b0 = Bs[ k2q      * P2 + cn];
            uint2 b1 = Bs[(k2q + 4) * P2 + cn];
            mma_bf16(acc[nt], ah, b0.x, b1.x);
            mma_bf16(acc[nt], ah, b0.y, b1.y);
            mma_bf16(acc[nt], al, b0.x, b1.x);
        }

        if (t + 1 < nk) STORE((t + 1) & 1);
        __syncthreads();
    }

    #pragma unroll
    for (int nt = 0; nt < 8; nt++) {
        int row = m0 + wm + (lane >> 2);
        int col = (nt << 3) + ((lane & 3) << 1);
        Cq[(size_t)row * (C_ / 2) + (col >> 1)]       = packpair(acc[nt][0], acc[nt][1]);
        Cq[(size_t)(row + 8) * (C_ / 2) + (col >> 1)] = packpair(acc[nt][2], acc[nt][3]);
    }
}

// ---------------------------------------------------------------------------
// Weight pre-pack (vectorized: 4 outputs/thread): rows paired -> PP uint2
// N % 4 == 0 for all weights here.
// ---------------------------------------------------------------------------
__global__ void pack_w(const float* __restrict__ src, uint2* __restrict__ dst,
                       int halfRows, int N)
{
    int i = blockIdx.x * 256 + threadIdx.x;      // quad index
    int total = halfRows * (N >> 2);
    if (i < total) {
        int g = i / (N >> 2), jq = i - g * (N >> 2);
        int j = jq << 2;
        float4 r0 = *(const float4*)(src + (size_t)(2 * g)     * N + j);
        float4 r1 = *(const float4*)(src + (size_t)(2 * g + 1) * N + j);
        uint4 o0, o1;
        uint2 p;
        p = packpair(r0.x, r1.x); o0.x = p.x; o0.y = p.y;
        p = packpair(r0.y, r1.y); o0.z = p.x; o0.w = p.y;
        p = packpair(r0.z, r1.z); o1.x = p.x; o1.y = p.y;
        p = packpair(r0.w, r1.w); o1.z = p.x; o1.w = p.y;
        uint4* d4 = (uint4*)(dst + (size_t)g * N + j);
        d4[0] = o0; d4[1] = o1;
    }
}

// Pack Wq/Wk/Wv [L][C][C] -> PP Wcat [L][C/2][3C]
__global__ void pack_qkv_pp(const float* __restrict__ Wq, const float* __restrict__ Wk,
                            const float* __restrict__ Wv, uint2* __restrict__ Wcat)
{
    int i = blockIdx.x * 256 + threadIdx.x;
    if (i < L_ * (C_ / 2) * C_) {
        int l  = i / ((C_ / 2) * C_);
        int rm = i - l * ((C_ / 2) * C_);
        int k2 = rm / C_, j = rm - k2 * C_;
        size_t so = (size_t)l * C_ * C_;
        uint2* W = Wcat + (size_t)l * (C_ / 2) * C3_ + (size_t)k2 * C3_;
        W[j]          = packpair(Wq[so + (size_t)(2*k2) * C_ + j], Wq[so + (size_t)(2*k2+1) * C_ + j]);
        W[C_ + j]     = packpair(Wk[so + (size_t)(2*k2) * C_ + j], Wk[so + (size_t)(2*k2+1) * C_ + j]);
        W[2 * C_ + j] = packpair(Wv[so + (size_t)(2*k2) * C_ + j], Wv[so + (size_t)(2*k2+1) * C_ + j]);
    }
}

// ---------------------------------------------------------------------------
// LayerNorm (biased variance, eps=1e-5) -> PP uint2 output
// ---------------------------------------------------------------------------
__global__ void layernorm_pp(const float* __restrict__ x, const float* __restrict__ g,
                             const float* __restrict__ b, uint2* __restrict__ y)
{
    int row = blockIdx.x;
    const float* xr = x + (size_t)row * C_;
    uint2* yr       = y + (size_t)row * (C_ / 2);
    int tid = threadIdx.x;
    float s = 0.f, s2 = 0.f;
    for (int c = tid; c < C_; c += 256) { float v = xr[c]; s += v; s2 += v * v; }
    __shared__ float shs[8], shs2[8];
    #pragma unroll
    for (int o = 16; o; o >>= 1) {
        s  += __shfl_xor_sync(0xffffffffu, s,  o);
        s2 += __shfl_xor_sync(0xffffffffu, s2, o);
    }
    if ((tid & 31) == 0) { shs[tid >> 5] = s; shs2[tid >> 5] = s2; }
    __syncthreads();
    float ts = 0.f, ts2 = 0.f;
    #pragma unroll
    for (int i = 0; i < 8; i++) { ts += shs[i]; ts2 += shs2[i]; }
    float mean = ts * (1.f / C_);
    float var  = ts2 * (1.f / C_) - mean * mean;
    float rstd = rsqrtf(var + 1e-5f);
    for (int p = tid; p < C_ / 2; p += 256) {
        float2 xv = ((const float2*)xr)[p];
        float2 gv = ((const float2*)g)[p];
        float2 bv = ((const float2*)b)[p];
        yr[p] = packpair((xv.x - mean) * rstd * gv.x + bv.x,
                         (xv.y - mean) * rstd * gv.y + bv.y);
    }
}

// ---------------------------------------------------------------------------
// Causal softmax: read plain float att row, write SPLIT-PACKED uint2 pairs
// in place. Writes only to the next 128 boundary. __expf for speed.
// ---------------------------------------------------------------------------
__global__ void softmax_causal(float* __restrict__ att)
{
    int row = blockIdx.x;             // b*H*T + h*T + q
    int q   = row & (T_ - 1);
    float* a = att + (size_t)row * T_;
    uint2* apk = (uint2*)a;
    int len  = q + 1;
    int wlim = ((q >> 7) + 1) << 7;
    int tid  = threadIdx.x;
    __shared__ float sh[8];

    float r[4];
    #pragma unroll
    for (int i = 0; i < 2; i++) {
        int p = tid + (i << 8);
        float2 v = ((const float2*)a)[p];
        r[2*i]     = (2*p     < len) ? v.x : -3.0e38f;
        r[2*i + 1] = (2*p + 1 < len) ? v.y : -3.0e38f;
    }
    float mx = fmaxf(fmaxf(r[0], r[1]), fmaxf(r[2], r[3]));
    #pragma unroll
    for (int o = 16; o; o >>= 1) mx = fmaxf(mx, __shfl_xor_sync(0xffffffffu, mx, o));
    if ((tid & 31) == 0) sh[tid >> 5] = mx;
    __syncthreads();
    mx = sh[0];
    #pragma unroll
    for (int i = 1; i < 8; i++) mx = fmaxf(mx, sh[i]);
    __syncthreads();

    float s = 0.f;
    #pragma unroll
    for (int i = 0; i < 2; i++) {
        int p = tid + (i << 8);
        r[2*i]     = (2*p     < len) ? __expf(r[2*i]     - mx) : 0.f;
        r[2*i + 1] = (2*p + 1 < len) ? __expf(r[2*i + 1] - mx) : 0.f;
        s += r[2*i] + r[2*i + 1];
    }
    #pragma unroll
    for (int o = 16; o; o >>= 1) s += __shfl_xor_sync(0xffffffffu, s, o);
    if ((tid & 31) == 0) sh[tid >> 5] = s;
    __syncthreads();
    float tot = 0.f;
    #pragma unroll
    for (int i = 0; i < 8; i++) tot += sh[i];
    float inv = 1.f / tot;

    #pragma unroll
    for (int i = 0; i < 2; i++) {
        int p = tid + (i << 8);
        if (2 * p < wlim)
            apk[p] = packpair(r[2*i] * inv, r[2*i + 1] * inv);
    }
}

// ---------------------------------------------------------------------------
// Embedding
// ---------------------------------------------------------------------------
__global__ void embed_k(const int* __restrict__ idx, const float* __restrict__ tok,
                        const float* __restrict__ pos, float* __restrict__ x)
{
    int r = blockIdx.x;
    int t = r & (T_ - 1);
    int token = idx[r];
    const float* te = tok + (size_t)token * C_;
    const float* pe = pos + (size_t)t * C_;
    float* xr = x + (size_t)r * C_;
    for (int c = threadIdx.x; c < C_; c += 256) xr[c] = te[c] + pe[c];
}

// ---------------------------------------------------------------------------
// Launch
// ---------------------------------------------------------------------------
extern "C" void kernel_launch(void* const* d_in, const int* in_sizes, int n_in,
                              void* d_out, int out_size)
{
    (void)in_sizes; (void)n_in; (void)out_size;
    const int*   idx = (const int*)d_in[0];
    const float* tok = (const float*)d_in[1];
    const float* pos = (const float*)d_in[2];
    const float* Wq  = (const float*)d_in[3];
    const float* Wk  = (const float*)d_in[4];
    const float* Wv  = (const float*)d_in[5];
    const float* Wp  = (const float*)d_in[6];
    const float* bp  = (const float*)d_in[7];
    const float* g1  = (const float*)d_in[8];
    const float* be1 = (const float*)d_in[9];
    const float* g2  = (const float*)d_in[10];
    const float* be2 = (const float*)d_in[11];
    const float* W1  = (const float*)d_in[12];
    const float* bb1 = (const float*)d_in[13];
    const float* W2  = (const float*)d_in[14];
    const float* bb2 = (const float*)d_in[15];
    const float* gf  = (const float*)d_in[16];
    const float* bf  = (const float*)d_in[17];
    const float* Wh  = (const float*)d_in[18];
    const float* bhd = (const float*)d_in[19];
    float* out = (float*)d_out;

    float    *x, *att;
    unsigned *qkv2;
    uint2    *h2, *o2, *a12, *wcat2, *wp2, *w12, *w22, *wh2;
    cudaGetSymbolAddress((void**)&x,     g_x);
    cudaGetSymbolAddress((void**)&h2,    g_h2);
    cudaGetSymbolAddress((void**)&qkv2,  g_qkv2);
    cudaGetSymbolAddress((void**)&o2,    g_o2);
    cudaGetSymbolAddress((void**)&a12,   g_a12);
    cudaGetSymbolAddress((void**)&att,   g_att);
    cudaGetSymbolAddress((void**)&wcat2, g_wcat2);
    cudaGetSymbolAddress((void**)&wp2,   g_wp2);
    cudaGetSymbolAddress((void**)&w12,   g_w12);
    cudaGetSymbolAddress((void**)&w22,   g_w22);
    cudaGetSymbolAddress((void**)&wh2,   g_wh2);

    cudaFuncSetAttribute((const void*)gemm_lin,
                         cudaFuncAttributeMaxDynamicSharedMemorySize, (int)SMEM_LIN);
    cudaFuncSetAttribute((const void*)gemm_lin64,
                         cudaFuncAttributeMaxDynamicSharedMemorySize, (int)SMEM_L64);

    const float att_scale = 0.03608439182435161f;  // 768^-0.5 (reference uses full C)
    const float* NOF = (const float*)0;

    embed_k<<<BT_, 256>>>(idx, tok, pos, x);

    // --- pre-split + pre-pack all weights (batched over layers) ---
    pack_qkv_pp<<<(L_ * (C_ / 2) * C_ + 255) / 256, 256>>>(Wq, Wk, Wv, wcat2);
    pack_w<<<(L_ * (C_ / 2) * (C_  / 4) + 255) / 256, 256>>>(Wp, wp2, L_ * C_ / 2, C_);
    pack_w<<<(L_ * (C_ / 2) * (C4_ / 4) + 255) / 256, 256>>>(W1, w12, L_ * C_ / 2, C4_);
    pack_w<<<(L_ * (C4_ / 2) * (C_ / 4) + 255) / 256, 256>>>(W2, w22, L_ * C4_ / 2, C_);
    pack_w<<<((C_ / 2) * (V_ / 4) + 255) / 256, 256>>>(Wh, wh2, C_ / 2, V_);

    dim3 gqkv(C3_ / 128, BT_ / 128, 1);
    dim3 gc64(C_  / 128, BT_ / 64,  1);     // 6 x 64 = 384 CTAs
    dim3 gsc (T_  / 128, T_  / 128, B_ * H_);
    dim3 gav (1,         T_  / 128, B_ * H_);
    dim3 gf1 (C4_ / 128, BT_ / 128, 1);

    for (int l = 0; l < L_; l++) {
        layernorm_pp<<<BT_, 256>>>(x, g1 + l * C_, be1 + l * C_, h2);

        // qkv = h @ Wcat -> EW u32 [BT][3C]
        gemm_lin<<<gqkv, 512, SMEM_LIN>>>(h2, wcat2 + (size_t)l * (C_/2) * C3_,
                (float*)qkv2, BT_, C3_, C_, NOF, NOF, 0, 1);

        // scores: Q @ K^T per (b,h) -> plain att, upper blocks skipped
        gemm_sc<<<gsc, 512, SMEM_SA>>>(qkv2, att, att_scale);

        softmax_causal<<<B_ * H_ * T_, 256>>>(att);

        // AV: P(PP) @ V -> o (PP), causally clamped K
        gemm_av<<<gav, 256, SMEM_SA>>>(att, qkv2, o2);

        // x = x + o @ Wproj + bproj  (64-row tiles, 384 CTAs)
        gemm_lin64<<<gc64, 256, SMEM_L64>>>(o2, wp2 + (size_t)l * (C_/2) * C_,
                x, C_, C_, bp + l * C_, x);

        layernorm_pp<<<BT_, 256>>>(x, g2 + l * C_, be2 + l * C_, h2);

        // a1 = gelu(h @ W1 + b1) -> PP
        gemm_lin<<<gf1, 512, SMEM_LIN>>>(h2, w12 + (size_t)l * (C_/2) * C4_,
                (float*)a12, BT_, C4_, C_, bb1 + l * C4_, NOF, 1, 2);

        // x = x + a1 @ W2 + b2  (64-row tiles, 384 CTAs)
        gemm_lin64<<<gc64, 256, SMEM_L64>>>(a12, w22 + (size_t)l * (C4_/2) * C_,
                x, C_, C4_, bb2 + l * C_, x);
    }

    layernorm_pp<<<BT_, 256>>>(x, gf, bf, h2);

    // head: 3-term bf16
    dim3 ghd(V_ / 128, BT_ / 128, 1);
    gemm_lin<<<ghd, 512, SMEM_LIN>>>(h2, wh2, out, BT_, V_, C_, bhd, NOF, 0, 0);
}